// round 2
// baseline (speedup 1.0000x reference)
#include <cuda_runtime.h>

#define DD 4096

typedef unsigned long long u64;

__device__ float g_dev[DD];

__global__ void compute_g_kernel(const float* __restrict__ eps,
                                 const float* __restrict__ g_mu,
                                 const float* __restrict__ g_rho) {
    int i = blockIdx.x * blockDim.x + threadIdx.x;
    if (i < DD) {
        float r = g_rho[i];
        g_dev[i] = g_mu[i] + log1pf(expf(r)) * eps[i];
    }
}

__device__ __forceinline__ u64 ADD2(u64 a, u64 b){ u64 c; asm("add.rn.f32x2 %0, %1, %2;" : "=l"(c) : "l"(a), "l"(b)); return c; }
__device__ __forceinline__ u64 SUB2(u64 a, u64 b){ u64 c; asm("sub.rn.f32x2 %0, %1, %2;" : "=l"(c) : "l"(a), "l"(b)); return c; }
__device__ __forceinline__ u64 MUL2(u64 a, u64 b){ u64 c; asm("mul.rn.f32x2 %0, %1, %2;" : "=l"(c) : "l"(a), "l"(b)); return c; }
__device__ __forceinline__ u64 PACK2(float lo, float hi){ u64 c; asm("mov.b64 %0, {%1, %2};" : "=l"(c) : "f"(lo), "f"(hi)); return c; }
__device__ __forceinline__ float2 UNPK(u64 v){ float2 r; asm("mov.b64 {%0, %1}, %2;" : "=f"(r.x), "=f"(r.y) : "l"(v)); return r; }

// Radix-64 FWHT over register index (6 butterfly stages), each u64 packs
// (rowA[i], rowB[i]) so every op is one packed f32x2 instruction.
__device__ __forceinline__ void fwht64(u64 v[64]) {
#pragma unroll
    for (int s = 0; s < 6; s++) {
        const int h = 1 << s;
#pragma unroll
        for (int q = 0; q < 64; q += 2*h) {
#pragma unroll
            for (int j = 0; j < h; j++) {
                u64 a = v[q+j], b = v[q+j+h];
                v[q+j]   = ADD2(a, b);
                v[q+j+h] = SUB2(a, b);
            }
        }
    }
}

// y_row = s1 * FWHT( g * FWHT( s2 * x_row ) )
// FWHT_4096 = FWHT over elem bits S2={0,1,6,7,8,9} (phases A and C, in regs)
//           x FWHT over elem bits S1={2,3,4,5,10,11} (phase B, in regs, fused
//             with the elementwise g multiply between the two transforms).
// Shared memory uses pad phys(i) = i + (i>>4) (u64 units). Both access
// patterns are conflict-free per 16-lane phase, and the pad arithmetic never
// carries, so every smem address is base_reg + compile-time immediate.
__global__ void __launch_bounds__(64, 6)
whvi_kernel(const float* __restrict__ x,
            const float* __restrict__ s1,
            const float* __restrict__ s2,
            float* __restrict__ out) {
    __shared__ u64 sm[DD + DD/16];   // 4096 + 256 pad = 34816 B

    const int t = threadIdx.x;                 // 0..63
    const long long rowA = 2LL * blockIdx.x;
    const float* xa = x + rowA * DD;
    const float* xb = xa + DD;

    // Phase A/C ownership: elem bits {2..5} = t&15, bits {10,11} = t>>4.
    const int baseA = 4 * (t & 15) + 1024 * (t >> 4);     // baseA & 15 <= 12
    const int physA = baseA + (baseA >> 4);
    // Phase B ownership: elem bits {0,1} = t&3, bits {6..9} = (t>>2)&15.
    const int baseB = (t & 3) + 64 * ((t >> 2) & 15);     // baseB & 15 <= 3
    const int physB = baseB + (baseB >> 4);

    u64 v[64];

    // ---- Phase A: coalesced load, *s2, FWHT over S2 bits, store ----
#pragma unroll
    for (int c = 0; c < 16; c++) {
        const int i = baseA + 64 * c;
        float4 a = *reinterpret_cast<const float4*>(xa + i);
        float4 b = *reinterpret_cast<const float4*>(xb + i);
        float4 s = *reinterpret_cast<const float4*>(s2 + i);
        v[4*c+0] = PACK2(a.x*s.x, b.x*s.x);
        v[4*c+1] = PACK2(a.y*s.y, b.y*s.y);
        v[4*c+2] = PACK2(a.z*s.z, b.z*s.z);
        v[4*c+3] = PACK2(a.w*s.w, b.w*s.w);
    }
    fwht64(v);
#pragma unroll
    for (int k = 0; k < 64; k++) {
        const int ck = (k & 3) + 64 * (k >> 2);           // ck & 15 <= 3
        sm[physA + ck + (ck >> 4)] = v[k];
    }
    __syncthreads();

    // ---- Phase B: FWHT over S1 bits, *g, FWHT over S1 bits again ----
#pragma unroll
    for (int k = 0; k < 64; k++) {
        const int ck = 4 * (k & 15) + 1024 * (k >> 4);    // ck & 15 <= 12
        v[k] = sm[physB + ck + (ck >> 4)];
    }
    fwht64(v);
#pragma unroll
    for (int k = 0; k < 64; k++) {
        const int ck = 4 * (k & 15) + 1024 * (k >> 4);
        const float gv = g_dev[baseB + ck];
        v[k] = MUL2(v[k], PACK2(gv, gv));
    }
    fwht64(v);
#pragma unroll
    for (int k = 0; k < 64; k++) {
        const int ck = 4 * (k & 15) + 1024 * (k >> 4);
        sm[physB + ck + (ck >> 4)] = v[k];
    }
    __syncthreads();

    // ---- Phase C: load, FWHT over S2 bits, *s1, coalesced store ----
#pragma unroll
    for (int k = 0; k < 64; k++) {
        const int ck = (k & 3) + 64 * (k >> 2);
        v[k] = sm[physA + ck + (ck >> 4)];
    }
    fwht64(v);

    float* oa = out + rowA * DD;
    float* ob = oa + DD;
#pragma unroll
    for (int c = 0; c < 16; c++) {
        const int i = baseA + 64 * c;
        float4 s = *reinterpret_cast<const float4*>(s1 + i);
        float2 p0 = UNPK(MUL2(v[4*c+0], PACK2(s.x, s.x)));
        float2 p1 = UNPK(MUL2(v[4*c+1], PACK2(s.y, s.y)));
        float2 p2 = UNPK(MUL2(v[4*c+2], PACK2(s.z, s.z)));
        float2 p3 = UNPK(MUL2(v[4*c+3], PACK2(s.w, s.w)));
        *reinterpret_cast<float4*>(oa + i) = make_float4(p0.x, p1.x, p2.x, p3.x);
        *reinterpret_cast<float4*>(ob + i) = make_float4(p0.y, p1.y, p2.y, p3.y);
    }
}

extern "C" void kernel_launch(void* const* d_in, const int* in_sizes, int n_in,
                              void* d_out, int out_size) {
    const float* x     = (const float*)d_in[0];
    const float* eps   = (const float*)d_in[1];
    const float* s1    = (const float*)d_in[2];
    const float* s2    = (const float*)d_in[3];
    const float* g_mu  = (const float*)d_in[4];
    const float* g_rho = (const float*)d_in[5];
    float* out = (float*)d_out;

    int B = in_sizes[0] / DD;   // 2048

    compute_g_kernel<<<(DD + 255) / 256, 256>>>(eps, g_mu, g_rho);
    whvi_kernel<<<B / 2, 64>>>(x, s1, s2, out);
}

// round 3
// speedup vs baseline: 2.8757x; 2.8757x over previous
#include <cuda_runtime.h>

#define DD 4096

__device__ float g_dev[DD];

__global__ void compute_g_kernel(const float* __restrict__ eps,
                                 const float* __restrict__ g_mu,
                                 const float* __restrict__ g_rho) {
    int i = blockIdx.x * blockDim.x + threadIdx.x;
    if (i < DD) {
        float r = g_rho[i];
        g_dev[i] = g_mu[i] + log1pf(expf(r)) * eps[i];
    }
}

// Universal bank swizzle: phys(i) = i ^ (((i>>5) ^ (i>>10)) & 31).
// Bank(i) = phys(i) % 32 is injective over each warp's 32-lane access set for
// all three phase layouts used below (verified bit-level per layout).
// Because each phase's base bits (lane/warp) and offset bits (register) are
// disjoint and carry-free, phys(base + c) = phys(base) ^ phys(c), with
// phys(c) a compile-time constant -> one LOP3 per shared access.
__device__ __forceinline__ int PHYS(int i) {
    return i ^ (((i >> 5) ^ (i >> 10)) & 31);
}

// Radix-16 FWHT over the register index (4 butterfly stages), scalar fp32.
__device__ __forceinline__ void fwht16(float v[16]) {
#pragma unroll
    for (int s = 0; s < 4; s++) {
        const int h = 1 << s;
#pragma unroll
        for (int q = 0; q < 16; q += 2*h) {
#pragma unroll
            for (int j = 0; j < h; j++) {
                float a = v[q+j], b = v[q+j+h];
                v[q+j]   = a + b;
                v[q+j+h] = a - b;
            }
        }
    }
}

// y_row = s1 * FWHT( g * FWHT( s2 * x_row ) ),  FWHT_4096 = F_A . F_B . F_C
// (tensor factors over disjoint element-bit groups; they commute).
//   Phase A: regs = bits {0..3},  lanes = bits {4..8},  warps = bits {9..11}
//   Phase B: regs = bits {4..7},  lanes = bits {0,1,2,8,9}, warps = {3,10,11}
//   Phase C: regs = bits {8..11}, lanes = bits {0..4},  warps = bits {5..7}
// Sequence: load*s2, F_A | F_B | F_C, *g, F_C | F_B | F_A*s1, store.
// One row per CTA; 4 shared round trips, all conflict-free 32-bit accesses.
__global__ void __launch_bounds__(256, 5)
whvi_kernel(const float* __restrict__ x,
            const float* __restrict__ s1,
            const float* __restrict__ s2,
            float* __restrict__ out) {
    __shared__ float sm[DD];

    const int t = threadIdx.x;
    const int l = t & 31;
    const int w = t >> 5;

    // Ownership bases (element index of register 0) per phase.
    const int baseA = 16*l + 512*w;
    const int baseB = (l & 7) + 8*(w & 1) + 256*(l >> 3) + 1024*(w >> 1);
    const int baseC = l + 32*w;
    const int pA = PHYS(baseA);
    const int pB = PHYS(baseB);
    const int pC = PHYS(baseC);

    const long long row = blockIdx.x;
    const float* xr = x + row * DD;

    float v[16];

    // ---- P1: coalesced load, *s2, F_A ----
#pragma unroll
    for (int q = 0; q < 4; q++) {
        float4 a = *reinterpret_cast<const float4*>(xr + baseA + 4*q);
        float4 s = *reinterpret_cast<const float4*>(s2 + baseA + 4*q);
        v[4*q+0] = a.x * s.x;
        v[4*q+1] = a.y * s.y;
        v[4*q+2] = a.z * s.z;
        v[4*q+3] = a.w * s.w;
    }
    fwht16(v);
#pragma unroll
    for (int r = 0; r < 16; r++) sm[pA ^ PHYS(r)] = v[r];
    __syncthreads();

    // ---- P2: F_B ----
#pragma unroll
    for (int r = 0; r < 16; r++) v[r] = sm[pB ^ PHYS(16*r)];
    fwht16(v);
#pragma unroll
    for (int r = 0; r < 16; r++) sm[pB ^ PHYS(16*r)] = v[r];
    __syncthreads();

    // ---- P3: F_C, *g, F_C ----
#pragma unroll
    for (int r = 0; r < 16; r++) v[r] = sm[pC ^ PHYS(256*r)];
    fwht16(v);
#pragma unroll
    for (int r = 0; r < 16; r++) v[r] *= g_dev[baseC + 256*r];
    fwht16(v);
#pragma unroll
    for (int r = 0; r < 16; r++) sm[pC ^ PHYS(256*r)] = v[r];
    __syncthreads();

    // ---- P4: F_B ----
#pragma unroll
    for (int r = 0; r < 16; r++) v[r] = sm[pB ^ PHYS(16*r)];
    fwht16(v);
#pragma unroll
    for (int r = 0; r < 16; r++) sm[pB ^ PHYS(16*r)] = v[r];
    __syncthreads();

    // ---- P5: F_A, *s1, coalesced store ----
#pragma unroll
    for (int r = 0; r < 16; r++) v[r] = sm[pA ^ PHYS(r)];
    fwht16(v);

    float* orow = out + row * DD;
#pragma unroll
    for (int q = 0; q < 4; q++) {
        float4 s = *reinterpret_cast<const float4*>(s1 + baseA + 4*q);
        float4 o;
        o.x = v[4*q+0] * s.x;
        o.y = v[4*q+1] * s.y;
        o.z = v[4*q+2] * s.z;
        o.w = v[4*q+3] * s.w;
        *reinterpret_cast<float4*>(orow + baseA + 4*q) = o;
    }
}

extern "C" void kernel_launch(void* const* d_in, const int* in_sizes, int n_in,
                              void* d_out, int out_size) {
    const float* x     = (const float*)d_in[0];
    const float* eps   = (const float*)d_in[1];
    const float* s1    = (const float*)d_in[2];
    const float* s2    = (const float*)d_in[3];
    const float* g_mu  = (const float*)d_in[4];
    const float* g_rho = (const float*)d_in[5];
    float* out = (float*)d_out;

    int B = in_sizes[0] / DD;   // 2048

    compute_g_kernel<<<(DD + 255) / 256, 256>>>(eps, g_mu, g_rho);
    whvi_kernel<<<B, 256>>>(x, s1, s2, out);
}